// round 7
// baseline (speedup 1.0000x reference)
#include <cuda_runtime.h>
#include <cfloat>
#include <math.h>

#define B_   16
#define NPER 2048
#define NTOT (B_*NPER)
#define KNN  20

typedef unsigned long long ull;

// ---------------- scratch (device globals; no runtime allocation) ----------
__device__ float4 g_x0[NTOT];
__device__ float  g_sn[NTOT];
__device__ int    g_idx[NTOT*KNN];
__device__ float  g_x1[NTOT*64];
__device__ float  g_x2[NTOT*64];
__device__ float  g_x3[NTOT*128];
__device__ float  g_u2[NTOT*64];
__device__ float  g_y2[NTOT*64];
__device__ float  g_u3[NTOT*128];
__device__ float  g_y3[NTOT*128];
__device__ float  g_out2[B_*1024];

__device__ __forceinline__ void atomicMaxFloat(float* addr, float v){
    if (v >= 0.f) atomicMax((int*)addr, __float_as_int(v));
    else          atomicMin((unsigned int*)addr, (unsigned int)__float_as_int(v));
}

// packed f32x2 helpers (Blackwell)
#define FMA2(d,a,b) asm("fma.rn.f32x2 %0, %1, %2, %0;" : "+l"(d) : "l"(a), "l"(b))

__device__ __forceinline__ ull dup2(float x){
    ull r; unsigned u = __float_as_uint(x);
    asm("mov.b64 %0, {%1, %1};" : "=l"(r) : "r"(u));
    return r;
}
__device__ __forceinline__ ull pack2(float lo, float hi){
    ull r;
    asm("mov.b64 %0, {%1, %2};" : "=l"(r) : "r"(__float_as_uint(lo)), "r"(__float_as_uint(hi)));
    return r;
}
__device__ __forceinline__ void unpack2(ull v, float& lo, float& hi){
    unsigned a, b;
    asm("mov.b64 {%0, %1}, %2;" : "=r"(a), "=r"(b) : "l"(v));
    lo = __uint_as_float(a); hi = __uint_as_float(b);
}

// ---------------- prep ------------------------------------------------------
__global__ __launch_bounds__(256) void x0_kernel(const float* __restrict__ pos,
                                                 const float* __restrict__ xf){
    int i = blockIdx.x*256 + threadIdx.x;
    g_x0[i] = make_float4(pos[i*3+0], pos[i*3+1], pos[i*3+2], xf[i]);
}
__global__ __launch_bounds__(256) void sn_kernel(){
    int i = blockIdx.x*256 + threadIdx.x;
    float4 p = g_x0[i];
    g_sn[i] = p.x*p.x + p.y*p.y + p.z*p.z + p.w*p.w;
}
__global__ void init_out2_kernel(){
    int t = blockIdx.x*blockDim.x + threadIdx.x;
    if (t < B_*1024) g_out2[t] = -FLT_MAX;
}

// ---------------- kNN: warp per query (R6 proven) ---------------------------
__global__ __launch_bounds__(512) void knn_kernel()
{
    __shared__ float4 sp[NPER];
    __shared__ float  sn[NPER];
    const unsigned FULL = 0xFFFFFFFFu;
    int b    = blockIdx.x >> 7;
    int base = b * NPER;
    for (int j = threadIdx.x; j < NPER; j += 512){
        sp[j] = g_x0[base+j];
        sn[j] = g_sn[base+j];
    }
    __syncthreads();

    int lane = threadIdx.x & 31;
    int q    = (blockIdx.x & 127)*16 + (threadIdx.x >> 5);
    float4 p = sp[q];
    float  pn = sn[q];

    float bd = FLT_MAX;
    int   bi = 0;
    float worst = FLT_MAX;

    for (int s = 0; s < NPER; s += 32){
        int j = s + lane;
        float4 c = sp[j];
        float d = pn + sn[j] - 2.f*(p.x*c.x + p.y*c.y + p.z*c.z + p.w*c.w);
        if (j == q) d = FLT_MAX;
        unsigned m = __ballot_sync(FULL, d < worst);
        while (m){
            int src = __ffs(m) - 1; m &= m - 1;
            float dn = __shfl_sync(FULL, d, src);
            if (dn < worst){
                unsigned wm = __ballot_sync(FULL, (lane < KNN) && (bd == worst));
                int slot = __ffs(wm) - 1;
                if (lane == slot){ bd = dn; bi = s + src; }
                float v = (lane < KNN) ? bd : -FLT_MAX;
                #pragma unroll
                for (int t = 16; t > 0; t >>= 1)
                    v = fmaxf(v, __shfl_xor_sync(FULL, v, t));
                worst = v;
            }
        }
    }
    if (lane < KNN) g_idx[(base+q)*KNN + lane] = base + bi;
}

// ---------------- EdgeConv1: fused MLP(8->64->64->64), f32x2 packed outputs -
// 4 nodes per block (128 threads). Thread handles outputs (lane, lane+32)
// packed in one f32x2 accumulator per edge. Weights pre-packed in smem as
// (w[c][o], w[c][o+32]); h values stored duplicated so broadcast ulonglong2
// loads feed FMA2 directly.
__global__ __launch_bounds__(128) void conv1_kernel(
    const float* __restrict__ w1, const float* __restrict__ b1,
    const float* __restrict__ w2, const float* __restrict__ b2,
    const float* __restrict__ w3, const float* __restrict__ b3)
{
    __shared__ float sW1 [4*64];
    __shared__ float sW1d[4*64];
    __shared__ ull   sW2p[32*66];     // [o-pair][col], stride 66 -> conflict-free
    __shared__ ull   sW3p[32*66];
    __shared__ float sb1[64];
    __shared__ ull   hD[4][4][64];    // [warp][edge][col], duplicated (v,v)

    for (int t = threadIdx.x; t < 32*64; t += 128){
        int o2 = t & 31, c = t >> 5;
        sW2p[o2*66 + c] = pack2(w2[c*64 + o2], w2[c*64 + o2 + 32]);
        sW3p[o2*66 + c] = pack2(w3[c*64 + o2], w3[c*64 + o2 + 32]);
    }
    for (int t = threadIdx.x; t < 4*64; t += 128){
        int c = t >> 6, o = t & 63;
        float top = w1[c*64+o], bot = w1[(c+4)*64+o];
        sW1[t] = bot; sW1d[t] = top - bot;
    }
    if (threadIdx.x < 64) sb1[threadIdx.x] = b1[threadIdx.x];
    __syncthreads();

    int wd = threadIdx.x >> 5, lane = threadIdx.x & 31;
    int i  = blockIdx.x * 4 + wd;
    int o0 = lane, o1 = lane + 32;
    float4 xi = g_x0[i];
    float base0 = sb1[o0] + xi.x*sW1d[o0] + xi.y*sW1d[64+o0] + xi.z*sW1d[128+o0] + xi.w*sW1d[192+o0];
    float base1 = sb1[o1] + xi.x*sW1d[o1] + xi.y*sW1d[64+o1] + xi.z*sW1d[128+o1] + xi.w*sW1d[192+o1];
    ull bp2 = pack2(b2[o0], b2[o1]);
    ull bp3 = pack2(b3[o0], b3[o1]);
    float mx0 = -FLT_MAX, mx1 = -FLT_MAX;
    const int* ip = g_idx + i*KNN;

    for (int kg = 0; kg < 5; kg++){
        // ---- layer1 (scalar; tiny) -> store h1 duplicated ----
        #pragma unroll
        for (int e=0;e<4;e++){
            int j = ip[kg*4+e];
            float4 xj = g_x0[j];
            float v0 = base0 + xj.x*sW1[o0] + xj.y*sW1[64+o0] + xj.z*sW1[128+o0] + xj.w*sW1[192+o0];
            float v1 = base1 + xj.x*sW1[o1] + xj.y*sW1[64+o1] + xj.z*sW1[128+o1] + xj.w*sW1[192+o1];
            v0 = fmaxf(v0, 0.f); v1 = fmaxf(v1, 0.f);
            hD[wd][e][o0] = dup2(v0);
            hD[wd][e][o1] = dup2(v1);
        }
        __syncwarp();
        // ---- layer2 (packed) ----
        ull acc[4] = {bp2, bp2, bp2, bp2};
        #pragma unroll
        for (int c4=0;c4<16;c4++){
            ulonglong2 wA = *(const ulonglong2*)(sW2p + lane*66 + c4*4);
            ulonglong2 wB = *(const ulonglong2*)(sW2p + lane*66 + c4*4 + 2);
            #pragma unroll
            for (int e=0;e<4;e++){
                ulonglong2 hA = *(const ulonglong2*)(&hD[wd][e][c4*4]);
                ulonglong2 hB = *(const ulonglong2*)(&hD[wd][e][c4*4 + 2]);
                FMA2(acc[e], hA.x, wA.x);
                FMA2(acc[e], hA.y, wA.y);
                FMA2(acc[e], hB.x, wB.x);
                FMA2(acc[e], hB.y, wB.y);
            }
        }
        __syncwarp();
        // ---- relu + store h2 duplicated ----
        #pragma unroll
        for (int e=0;e<4;e++){
            float lo, hi; unpack2(acc[e], lo, hi);
            lo = fmaxf(lo, 0.f); hi = fmaxf(hi, 0.f);
            hD[wd][e][o0] = dup2(lo);
            hD[wd][e][o1] = dup2(hi);
        }
        __syncwarp();
        // ---- layer3 (packed) ----
        ull acc3[4] = {bp3, bp3, bp3, bp3};
        #pragma unroll
        for (int c4=0;c4<16;c4++){
            ulonglong2 wA = *(const ulonglong2*)(sW3p + lane*66 + c4*4);
            ulonglong2 wB = *(const ulonglong2*)(sW3p + lane*66 + c4*4 + 2);
            #pragma unroll
            for (int e=0;e<4;e++){
                ulonglong2 hA = *(const ulonglong2*)(&hD[wd][e][c4*4]);
                ulonglong2 hB = *(const ulonglong2*)(&hD[wd][e][c4*4 + 2]);
                FMA2(acc3[e], hA.x, wA.x);
                FMA2(acc3[e], hA.y, wA.y);
                FMA2(acc3[e], hB.x, wB.x);
                FMA2(acc3[e], hB.y, wB.y);
            }
        }
        #pragma unroll
        for (int e=0;e<4;e++){
            float lo, hi; unpack2(acc3[e], lo, hi);
            mx0 = fmaxf(mx0, lo); mx1 = fmaxf(mx1, hi);
        }
        __syncwarp();
    }
    g_x1[i*64+o0] = mx0;
    g_x1[i*64+o1] = mx1;
}

// ---------------- node-level GEMM: U = X@(Wt-Wb), Y = X@Wb ------------------
__device__ __forceinline__ void uy_gemm_body(
    const float* __restrict__ X, const float* __restrict__ W,
    float* __restrict__ U, float* __restrict__ Y, int OUT)
{
    __shared__ float fbuf[64*33];
    __shared__ float wbuf[32*132];
    int nbase = blockIdx.x * 64;
    int otile = blockIdx.y * 128;
    int tn = threadIdx.x & 15;
    int to = threadIdx.x >> 4;

    float acc[4][8];
    #pragma unroll
    for (int r=0;r<4;r++)
        #pragma unroll
        for (int q=0;q<8;q++) acc[r][q]=0.f;

    for (int kc=0;kc<2;kc++){
        for (int t=threadIdx.x; t<64*32; t+=256){
            int n=t>>5, kk=t&31;
            fbuf[n*33+kk] = X[(nbase+n)*64 + kc*32 + kk];
        }
        for (int t=threadIdx.x; t<32*128; t+=256){
            int kk=t>>7, oloc=t&127;
            int op = otile + oloc;
            int k  = kc*32+kk;
            wbuf[kk*132+oloc] = (op < OUT)
                ? (W[k*OUT + op] - W[(64+k)*OUT + op])
                : W[(64+k)*OUT + (op-OUT)];
        }
        __syncthreads();
        #pragma unroll 4
        for (int kk=0;kk<32;kk++){
            float f[4];
            #pragma unroll
            for (int r=0;r<4;r++) f[r] = fbuf[(to+16*r)*33+kk];
            float wv[8];
            #pragma unroll
            for (int q=0;q<8;q++) wv[q] = wbuf[kk*132 + tn + 16*q];
            #pragma unroll
            for (int r=0;r<4;r++)
                #pragma unroll
                for (int q=0;q<8;q++) acc[r][q] += f[r]*wv[q];
        }
        __syncthreads();
    }
    #pragma unroll
    for (int r=0;r<4;r++){
        int node = nbase + to + 16*r;
        #pragma unroll
        for (int q=0;q<8;q++){
            int op = otile + tn + 16*q;
            if (op < OUT) U[node*OUT + op]        = acc[r][q];
            else          Y[node*OUT + (op-OUT)]  = acc[r][q];
        }
    }
}

__global__ __launch_bounds__(256) void uy_gemm2_kernel(const float* __restrict__ W){
    uy_gemm_body(g_x1, W, g_u2, g_y2, 64);
}
__global__ __launch_bounds__(256) void uy_gemm3_kernel(const float* __restrict__ W){
    uy_gemm_body(g_x2, W, g_u3, g_y3, 128);
}

// ---------------- gather + elementwise max ----------------------------------
__global__ __launch_bounds__(256) void gathermax2_kernel(const float* __restrict__ b2){
    int wd = threadIdx.x >> 5, lane = threadIdx.x & 31;
    int i = blockIdx.x*8 + wd;
    const int* ip = g_idx + i*KNN;
    float2 mx = make_float2(-FLT_MAX, -FLT_MAX);
    #pragma unroll 5
    for (int t=0;t<KNN;t++){
        int j = ip[t];
        float2 v = *(const float2*)(g_y2 + j*64 + lane*2);
        mx.x = fmaxf(mx.x, v.x);
        mx.y = fmaxf(mx.y, v.y);
    }
    float2 u  = *(const float2*)(g_u2 + i*64 + lane*2);
    float2 bb = *(const float2*)(b2 + lane*2);
    float2 o;
    o.x = bb.x + u.x + mx.x;
    o.y = bb.y + u.y + mx.y;
    *(float2*)(g_x2 + i*64 + lane*2) = o;
}

__global__ __launch_bounds__(256) void gathermax3_kernel(const float* __restrict__ b3){
    int wd = threadIdx.x >> 5, lane = threadIdx.x & 31;
    int i = blockIdx.x*8 + wd;
    const int* ip = g_idx + i*KNN;
    float4 mx = make_float4(-FLT_MAX,-FLT_MAX,-FLT_MAX,-FLT_MAX);
    #pragma unroll 5
    for (int t=0;t<KNN;t++){
        int j = ip[t];
        float4 v = *(const float4*)(g_y3 + j*128 + lane*4);
        mx.x = fmaxf(mx.x, v.x);
        mx.y = fmaxf(mx.y, v.y);
        mx.z = fmaxf(mx.z, v.z);
        mx.w = fmaxf(mx.w, v.w);
    }
    float4 u  = *(const float4*)(g_u3 + i*128 + lane*4);
    float4 bb = *(const float4*)(b3 + lane*4);
    float4 o;
    o.x = bb.x + u.x + mx.x;
    o.y = bb.y + u.y + mx.y;
    o.z = bb.z + u.z + mx.z;
    o.w = bb.w + u.w + mx.w;
    *(float4*)(g_x3 + i*128 + lane*4) = o;
}

// ---------------- lin1 (256->1024) + global max pool, f32x2 (R5 proven) ----
__global__ __launch_bounds__(256) void lin1max_kernel(
    const float* __restrict__ l1w, const float* __restrict__ l1b)
{
    __shared__ float fbufT[32*68];       // [kk][node]
    __shared__ float wbuf[32*260];       // [kk][o] (o < 256)
    int g     = blockIdx.x >> 5;
    int nbase = g*NPER + (blockIdx.x & 31)*64;
    int tn = threadIdx.x & 31;
    int to = threadIdx.x >> 5;

    for (int oc=0; oc<4; ++oc){
        ull acc2[4][8];
        #pragma unroll
        for (int np=0;np<4;np++)
            #pragma unroll
            for (int q=0;q<8;q++) acc2[np][q] = 0ull;

        for (int kc=0;kc<8;kc++){
            for (int t=threadIdx.x; t<64*32; t+=256){
                int n = t>>5, kk = t&31;
                int kglob = kc*32+kk;
                int node  = nbase + n;
                float v;
                if (kglob < 64)       v = g_x1[node*64  + kglob];
                else if (kglob < 128) v = g_x2[node*64  + (kglob-64)];
                else                  v = g_x3[node*128 + (kglob-128)];
                fbufT[kk*68+n] = v;
            }
            for (int t=threadIdx.x; t<32*256; t+=256){
                int kk = t>>8, o = t&255;
                wbuf[kk*260+o] = l1w[(kc*32+kk)*1024 + oc*256 + o];
            }
            __syncthreads();
            #pragma unroll 4
            for (int kk=0;kk<32;kk++){
                ulonglong2 fA = *(const ulonglong2*)(fbufT + kk*68 + to*8);
                ulonglong2 fB = *(const ulonglong2*)(fbufT + kk*68 + to*8 + 4);
                float4 wA = *(const float4*)(wbuf + kk*260 + tn*8);
                float4 wB = *(const float4*)(wbuf + kk*260 + tn*8 + 4);
                ull wd0 = dup2(wA.x), wd1 = dup2(wA.y);
                ull wd2 = dup2(wA.z), wd3 = dup2(wA.w);
                ull wd4 = dup2(wB.x), wd5 = dup2(wB.y);
                ull wd6 = dup2(wB.z), wd7 = dup2(wB.w);
                ull fp[4] = {fA.x, fA.y, fB.x, fB.y};
                #pragma unroll
                for (int np=0;np<4;np++){
                    FMA2(acc2[np][0], fp[np], wd0);
                    FMA2(acc2[np][1], fp[np], wd1);
                    FMA2(acc2[np][2], fp[np], wd2);
                    FMA2(acc2[np][3], fp[np], wd3);
                    FMA2(acc2[np][4], fp[np], wd4);
                    FMA2(acc2[np][5], fp[np], wd5);
                    FMA2(acc2[np][6], fp[np], wd6);
                    FMA2(acc2[np][7], fp[np], wd7);
                }
            }
            __syncthreads();
        }
        float m[8];
        #pragma unroll
        for (int q=0;q<8;q++){
            float best = -FLT_MAX;
            #pragma unroll
            for (int np=0;np<4;np++){
                float lo, hi; unpack2(acc2[np][q], lo, hi);
                best = fmaxf(best, fmaxf(lo, hi));
            }
            m[q] = best;
        }
        #pragma unroll
        for (int q=0;q<8;q++) wbuf[to*260 + tn*8 + q] = m[q];
        __syncthreads();
        {
            int o = threadIdx.x;
            float v = wbuf[o];
            #pragma unroll
            for (int t2=1;t2<8;t2++) v = fmaxf(v, wbuf[t2*260 + o]);
            v += l1b[oc*256 + o];
            atomicMaxFloat(&g_out2[g*1024 + oc*256 + o], v);
        }
        __syncthreads();
    }
}

// ---------------- head: MLP(1024->512->256->10) + log_softmax --------------
__global__ __launch_bounds__(256) void head_kernel(
    const float* __restrict__ m1w, const float* __restrict__ m1b,
    const float* __restrict__ m2w, const float* __restrict__ m2b,
    const float* __restrict__ m3w, const float* __restrict__ m3b,
    float* __restrict__ out)
{
    __shared__ float v[1024];
    __shared__ float h1[512];
    __shared__ float h2[256];
    __shared__ float z[10];
    int g = blockIdx.x;
    for (int t=threadIdx.x; t<1024; t+=256) v[t] = g_out2[g*1024+t];
    __syncthreads();
    #pragma unroll
    for (int oo=0;oo<2;oo++){
        int o = threadIdx.x + oo*256;
        float a = m1b[o];
        #pragma unroll 4
        for (int k=0;k<1024;k++) a += v[k]*m1w[k*512+o];
        h1[o] = fmaxf(a, 0.f);
    }
    __syncthreads();
    {
        int o = threadIdx.x;
        float a = m2b[o];
        #pragma unroll 4
        for (int k=0;k<512;k++) a += h1[k]*m2w[k*256+o];
        h2[o] = fmaxf(a, 0.f);
    }
    __syncthreads();
    if (threadIdx.x < 10){
        float a = m3b[threadIdx.x];
        for (int k=0;k<256;k++) a += h2[k]*m3w[k*10+threadIdx.x];
        z[threadIdx.x] = a;
    }
    __syncthreads();
    if (threadIdx.x == 0){
        float m = -FLT_MAX;
        for (int c=0;c<10;c++) m = fmaxf(m, z[c]);
        float s = 0.f;
        for (int c=0;c<10;c++) s += expf(z[c]-m);
        float l = logf(s);
        for (int c=0;c<10;c++) out[g*10+c] = z[c]-m-l;
    }
}

// ---------------- launch ----------------------------------------------------
extern "C" void kernel_launch(void* const* d_in, const int* in_sizes, int n_in,
                              void* d_out, int out_size)
{
    const float* pos  = (const float*)d_in[0];
    const float* xf   = (const float*)d_in[1];
    const float* c1w1 = (const float*)d_in[3];
    const float* c1b1 = (const float*)d_in[4];
    const float* c1w2 = (const float*)d_in[5];
    const float* c1b2 = (const float*)d_in[6];
    const float* c1w3 = (const float*)d_in[7];
    const float* c1b3 = (const float*)d_in[8];
    const float* c2w  = (const float*)d_in[9];
    const float* c2b  = (const float*)d_in[10];
    const float* c3w  = (const float*)d_in[11];
    const float* c3b  = (const float*)d_in[12];
    const float* l1w  = (const float*)d_in[13];
    const float* l1b  = (const float*)d_in[14];
    const float* m1w  = (const float*)d_in[15];
    const float* m1b  = (const float*)d_in[16];
    const float* m2w  = (const float*)d_in[17];
    const float* m2b  = (const float*)d_in[18];
    const float* m3w  = (const float*)d_in[19];
    const float* m3b  = (const float*)d_in[20];
    float* out = (float*)d_out;

    x0_kernel<<<NTOT/256, 256>>>(pos, xf);                         // 0
    sn_kernel<<<NTOT/256, 256>>>();                                // 1
    knn_kernel<<<NTOT/16, 512>>>();                                // 2
    conv1_kernel<<<NTOT/4, 128>>>(c1w1,c1b1,c1w2,c1b2,c1w3,c1b3);  // 3 (profiled)
    init_out2_kernel<<<(B_*1024+255)/256, 256>>>();                // 4
    uy_gemm2_kernel<<<dim3(NTOT/64, 1), 256>>>(c2w);
    gathermax2_kernel<<<NTOT/8, 256>>>(c2b);
    uy_gemm3_kernel<<<dim3(NTOT/64, 2), 256>>>(c3w);
    gathermax3_kernel<<<NTOT/8, 256>>>(c3b);
    lin1max_kernel<<<B_*32, 256>>>(l1w, l1b);
    head_kernel<<<B_, 256>>>(m1w,m1b,m2w,m2b,m3w,m3b,out);
}

// round 8
// speedup vs baseline: 1.1457x; 1.1457x over previous
#include <cuda_runtime.h>
#include <cfloat>
#include <math.h>

#define B_   16
#define NPER 2048
#define NTOT (B_*NPER)
#define KNN  20

typedef unsigned long long ull;

// ---------------- scratch (device globals; no runtime allocation) ----------
__device__ float4 g_x0[NTOT];
__device__ float  g_sn[NTOT];
__device__ int    g_idx[NTOT*KNN];
__device__ float  g_x1[NTOT*64];
__device__ float  g_x2[NTOT*64];
__device__ float  g_x3[NTOT*128];
__device__ float  g_u2[NTOT*64];
__device__ float  g_y2[NTOT*64];
__device__ float  g_u3[NTOT*128];
__device__ float  g_y3[NTOT*128];
__device__ float  g_out2[B_*1024];

__device__ __forceinline__ void atomicMaxFloat(float* addr, float v){
    if (v >= 0.f) atomicMax((int*)addr, __float_as_int(v));
    else          atomicMin((unsigned int*)addr, (unsigned int)__float_as_int(v));
}

// packed f32x2 helpers (Blackwell)
#define FMA2(d,a,b) asm("fma.rn.f32x2 %0, %1, %2, %0;" : "+l"(d) : "l"(a), "l"(b))

__device__ __forceinline__ ull dup2(float x){
    ull r; unsigned u = __float_as_uint(x);
    asm("mov.b64 %0, {%1, %1};" : "=l"(r) : "r"(u));
    return r;
}
__device__ __forceinline__ void unpack2(ull v, float& lo, float& hi){
    unsigned a, b;
    asm("mov.b64 {%0, %1}, %2;" : "=r"(a), "=r"(b) : "l"(v));
    lo = __uint_as_float(a); hi = __uint_as_float(b);
}

// ---------------- prep ------------------------------------------------------
__global__ __launch_bounds__(256) void x0_kernel(const float* __restrict__ pos,
                                                 const float* __restrict__ xf){
    int i = blockIdx.x*256 + threadIdx.x;
    g_x0[i] = make_float4(pos[i*3+0], pos[i*3+1], pos[i*3+2], xf[i]);
}
__global__ __launch_bounds__(256) void sn_kernel(){
    int i = blockIdx.x*256 + threadIdx.x;
    float4 p = g_x0[i];
    g_sn[i] = p.x*p.x + p.y*p.y + p.z*p.z + p.w*p.w;
}
__global__ void init_out2_kernel(){
    int t = blockIdx.x*blockDim.x + threadIdx.x;
    if (t < B_*1024) g_out2[t] = -FLT_MAX;
}

// ---------------- kNN: warp per query (R6 proven) ---------------------------
__global__ __launch_bounds__(512) void knn_kernel()
{
    __shared__ float4 sp[NPER];
    __shared__ float  sn[NPER];
    const unsigned FULL = 0xFFFFFFFFu;
    int b    = blockIdx.x >> 7;
    int base = b * NPER;
    for (int j = threadIdx.x; j < NPER; j += 512){
        sp[j] = g_x0[base+j];
        sn[j] = g_sn[base+j];
    }
    __syncthreads();

    int lane = threadIdx.x & 31;
    int q    = (blockIdx.x & 127)*16 + (threadIdx.x >> 5);
    float4 p = sp[q];
    float  pn = sn[q];

    float bd = FLT_MAX;
    int   bi = 0;
    float worst = FLT_MAX;

    for (int s = 0; s < NPER; s += 32){
        int j = s + lane;
        float4 c = sp[j];
        float d = pn + sn[j] - 2.f*(p.x*c.x + p.y*c.y + p.z*c.z + p.w*c.w);
        if (j == q) d = FLT_MAX;
        unsigned m = __ballot_sync(FULL, d < worst);
        while (m){
            int src = __ffs(m) - 1; m &= m - 1;
            float dn = __shfl_sync(FULL, d, src);
            if (dn < worst){
                unsigned wm = __ballot_sync(FULL, (lane < KNN) && (bd == worst));
                int slot = __ffs(wm) - 1;
                if (lane == slot){ bd = dn; bi = s + src; }
                float v = (lane < KNN) ? bd : -FLT_MAX;
                #pragma unroll
                for (int t = 16; t > 0; t >>= 1)
                    v = fmaxf(v, __shfl_xor_sync(FULL, v, t));
                worst = v;
            }
        }
    }
    if (lane < KNN) g_idx[(base+q)*KNN + lane] = base + bi;
}

// ---------------- EdgeConv1: col-packed FMA2, 10-edge batches ---------------
// Same smem layouts/bytes as the proven scalar version; inner GEMMs use
// fma.rn.f32x2 over adjacent column pairs (final = lo+hi). Weights amortized
// over 10 edges per pass; h stored plain (broadcast ull loads, no dup).
__global__ __launch_bounds__(128) void conv1_kernel(
    const float* __restrict__ w1, const float* __restrict__ b1,
    const float* __restrict__ w2, const float* __restrict__ b2,
    const float* __restrict__ w3, const float* __restrict__ b3)
{
    __shared__ __align__(16) float sW1 [4*64];
    __shared__ __align__(16) float sW1d[4*64];
    __shared__ __align__(16) float sW2t[64*68];   // [o][c], stride 68
    __shared__ __align__(16) float sW3t[64*68];
    __shared__ float sb1[64];
    __shared__ __align__(16) float hb[4][10][64]; // [warp][edge][col]

    for (int t = threadIdx.x; t < 64*64; t += 128){
        int c = t >> 6, o = t & 63;
        sW2t[o*68+c] = w2[t];
        sW3t[o*68+c] = w3[t];
    }
    for (int t = threadIdx.x; t < 4*64; t += 128){
        int c = t >> 6, o = t & 63;
        float top = w1[c*64+o], bot = w1[(c+4)*64+o];
        sW1[t] = bot; sW1d[t] = top - bot;
    }
    if (threadIdx.x < 64) sb1[threadIdx.x] = b1[threadIdx.x];
    __syncthreads();

    int wd = threadIdx.x >> 5, lane = threadIdx.x & 31;
    int i  = blockIdx.x * 4 + wd;
    int o0 = lane, o1 = lane + 32;
    float4 xi = g_x0[i];
    float base0 = sb1[o0] + xi.x*sW1d[o0] + xi.y*sW1d[64+o0] + xi.z*sW1d[128+o0] + xi.w*sW1d[192+o0];
    float base1 = sb1[o1] + xi.x*sW1d[o1] + xi.y*sW1d[64+o1] + xi.z*sW1d[128+o1] + xi.w*sW1d[192+o1];
    float b2v0 = b2[o0], b2v1 = b2[o1];
    float b3v0 = b3[o0], b3v1 = b3[o1];
    float mx0 = -FLT_MAX, mx1 = -FLT_MAX;
    const int* ip = g_idx + i*KNN;

    for (int half = 0; half < 2; half++){
        // ---- layer1: 10 edges, scalar (tiny), store h plain ----
        #pragma unroll
        for (int e=0;e<10;e++){
            int j = ip[half*10 + e];
            float4 xj = g_x0[j];
            float v0 = base0 + xj.x*sW1[o0] + xj.y*sW1[64+o0] + xj.z*sW1[128+o0] + xj.w*sW1[192+o0];
            float v1 = base1 + xj.x*sW1[o1] + xj.y*sW1[64+o1] + xj.z*sW1[128+o1] + xj.w*sW1[192+o1];
            hb[wd][e][o0] = fmaxf(v0, 0.f);
            hb[wd][e][o1] = fmaxf(v1, 0.f);
        }
        __syncwarp();
        // ---- layer2: col-packed FMA2 ----
        ull a0[10], a1[10];
        #pragma unroll
        for (int e=0;e<10;e++){ a0[e]=0ull; a1[e]=0ull; }
        #pragma unroll
        for (int c8=0;c8<8;c8++){
            ulonglong2 w0a = *(const ulonglong2*)(sW2t + o0*68 + c8*8);
            ulonglong2 w0b = *(const ulonglong2*)(sW2t + o0*68 + c8*8 + 4);
            ulonglong2 w1a = *(const ulonglong2*)(sW2t + o1*68 + c8*8);
            ulonglong2 w1b = *(const ulonglong2*)(sW2t + o1*68 + c8*8 + 4);
            #pragma unroll
            for (int e=0;e<10;e++){
                ulonglong2 ha = *(const ulonglong2*)(&hb[wd][e][c8*8]);
                ulonglong2 hbv = *(const ulonglong2*)(&hb[wd][e][c8*8 + 4]);
                FMA2(a0[e], ha.x,  w0a.x);
                FMA2(a0[e], ha.y,  w0a.y);
                FMA2(a0[e], hbv.x, w0b.x);
                FMA2(a0[e], hbv.y, w0b.y);
                FMA2(a1[e], ha.x,  w1a.x);
                FMA2(a1[e], ha.y,  w1a.y);
                FMA2(a1[e], hbv.x, w1b.x);
                FMA2(a1[e], hbv.y, w1b.y);
            }
        }
        __syncwarp();
        // ---- relu(lo+hi+b2) -> h2 plain ----
        #pragma unroll
        for (int e=0;e<10;e++){
            float lo, hi;
            unpack2(a0[e], lo, hi);
            hb[wd][e][o0] = fmaxf(lo + hi + b2v0, 0.f);
            unpack2(a1[e], lo, hi);
            hb[wd][e][o1] = fmaxf(lo + hi + b2v1, 0.f);
        }
        __syncwarp();
        // ---- layer3: col-packed FMA2 ----
        #pragma unroll
        for (int e=0;e<10;e++){ a0[e]=0ull; a1[e]=0ull; }
        #pragma unroll
        for (int c8=0;c8<8;c8++){
            ulonglong2 w0a = *(const ulonglong2*)(sW3t + o0*68 + c8*8);
            ulonglong2 w0b = *(const ulonglong2*)(sW3t + o0*68 + c8*8 + 4);
            ulonglong2 w1a = *(const ulonglong2*)(sW3t + o1*68 + c8*8);
            ulonglong2 w1b = *(const ulonglong2*)(sW3t + o1*68 + c8*8 + 4);
            #pragma unroll
            for (int e=0;e<10;e++){
                ulonglong2 ha = *(const ulonglong2*)(&hb[wd][e][c8*8]);
                ulonglong2 hbv = *(const ulonglong2*)(&hb[wd][e][c8*8 + 4]);
                FMA2(a0[e], ha.x,  w0a.x);
                FMA2(a0[e], ha.y,  w0a.y);
                FMA2(a0[e], hbv.x, w0b.x);
                FMA2(a0[e], hbv.y, w0b.y);
                FMA2(a1[e], ha.x,  w1a.x);
                FMA2(a1[e], ha.y,  w1a.y);
                FMA2(a1[e], hbv.x, w1b.x);
                FMA2(a1[e], hbv.y, w1b.y);
            }
        }
        // ---- max epilogue ----
        #pragma unroll
        for (int e=0;e<10;e++){
            float lo, hi;
            unpack2(a0[e], lo, hi);
            mx0 = fmaxf(mx0, lo + hi + b3v0);
            unpack2(a1[e], lo, hi);
            mx1 = fmaxf(mx1, lo + hi + b3v1);
        }
        __syncwarp();
    }
    g_x1[i*64+o0] = mx0;
    g_x1[i*64+o1] = mx1;
}

// ---------------- node-level GEMM: U = X@(Wt-Wb), Y = X@Wb ------------------
__device__ __forceinline__ void uy_gemm_body(
    const float* __restrict__ X, const float* __restrict__ W,
    float* __restrict__ U, float* __restrict__ Y, int OUT)
{
    __shared__ float fbuf[64*33];
    __shared__ float wbuf[32*132];
    int nbase = blockIdx.x * 64;
    int otile = blockIdx.y * 128;
    int tn = threadIdx.x & 15;
    int to = threadIdx.x >> 4;

    float acc[4][8];
    #pragma unroll
    for (int r=0;r<4;r++)
        #pragma unroll
        for (int q=0;q<8;q++) acc[r][q]=0.f;

    for (int kc=0;kc<2;kc++){
        for (int t=threadIdx.x; t<64*32; t+=256){
            int n=t>>5, kk=t&31;
            fbuf[n*33+kk] = X[(nbase+n)*64 + kc*32 + kk];
        }
        for (int t=threadIdx.x; t<32*128; t+=256){
            int kk=t>>7, oloc=t&127;
            int op = otile + oloc;
            int k  = kc*32+kk;
            wbuf[kk*132+oloc] = (op < OUT)
                ? (W[k*OUT + op] - W[(64+k)*OUT + op])
                : W[(64+k)*OUT + (op-OUT)];
        }
        __syncthreads();
        #pragma unroll 4
        for (int kk=0;kk<32;kk++){
            float f[4];
            #pragma unroll
            for (int r=0;r<4;r++) f[r] = fbuf[(to+16*r)*33+kk];
            float wv[8];
            #pragma unroll
            for (int q=0;q<8;q++) wv[q] = wbuf[kk*132 + tn + 16*q];
            #pragma unroll
            for (int r=0;r<4;r++)
                #pragma unroll
                for (int q=0;q<8;q++) acc[r][q] += f[r]*wv[q];
        }
        __syncthreads();
    }
    #pragma unroll
    for (int r=0;r<4;r++){
        int node = nbase + to + 16*r;
        #pragma unroll
        for (int q=0;q<8;q++){
            int op = otile + tn + 16*q;
            if (op < OUT) U[node*OUT + op]        = acc[r][q];
            else          Y[node*OUT + (op-OUT)]  = acc[r][q];
        }
    }
}

__global__ __launch_bounds__(256) void uy_gemm2_kernel(const float* __restrict__ W){
    uy_gemm_body(g_x1, W, g_u2, g_y2, 64);
}
__global__ __launch_bounds__(256) void uy_gemm3_kernel(const float* __restrict__ W){
    uy_gemm_body(g_x2, W, g_u3, g_y3, 128);
}

// ---------------- gather + elementwise max ----------------------------------
__global__ __launch_bounds__(256) void gathermax2_kernel(const float* __restrict__ b2){
    int wd = threadIdx.x >> 5, lane = threadIdx.x & 31;
    int i = blockIdx.x*8 + wd;
    const int* ip = g_idx + i*KNN;
    float2 mx = make_float2(-FLT_MAX, -FLT_MAX);
    #pragma unroll 5
    for (int t=0;t<KNN;t++){
        int j = ip[t];
        float2 v = *(const float2*)(g_y2 + j*64 + lane*2);
        mx.x = fmaxf(mx.x, v.x);
        mx.y = fmaxf(mx.y, v.y);
    }
    float2 u  = *(const float2*)(g_u2 + i*64 + lane*2);
    float2 bb = *(const float2*)(b2 + lane*2);
    float2 o;
    o.x = bb.x + u.x + mx.x;
    o.y = bb.y + u.y + mx.y;
    *(float2*)(g_x2 + i*64 + lane*2) = o;
}

__global__ __launch_bounds__(256) void gathermax3_kernel(const float* __restrict__ b3){
    int wd = threadIdx.x >> 5, lane = threadIdx.x & 31;
    int i = blockIdx.x*8 + wd;
    const int* ip = g_idx + i*KNN;
    float4 mx = make_float4(-FLT_MAX,-FLT_MAX,-FLT_MAX,-FLT_MAX);
    #pragma unroll 5
    for (int t=0;t<KNN;t++){
        int j = ip[t];
        float4 v = *(const float4*)(g_y3 + j*128 + lane*4);
        mx.x = fmaxf(mx.x, v.x);
        mx.y = fmaxf(mx.y, v.y);
        mx.z = fmaxf(mx.z, v.z);
        mx.w = fmaxf(mx.w, v.w);
    }
    float4 u  = *(const float4*)(g_u3 + i*128 + lane*4);
    float4 bb = *(const float4*)(b3 + lane*4);
    float4 o;
    o.x = bb.x + u.x + mx.x;
    o.y = bb.y + u.y + mx.y;
    o.z = bb.z + u.z + mx.z;
    o.w = bb.w + u.w + mx.w;
    *(float4*)(g_x3 + i*128 + lane*4) = o;
}

// ---------------- lin1 (256->1024) + global max pool, f32x2 (proven) -------
__global__ __launch_bounds__(256) void lin1max_kernel(
    const float* __restrict__ l1w, const float* __restrict__ l1b)
{
    __shared__ float fbufT[32*68];
    __shared__ float wbuf[32*260];
    int g     = blockIdx.x >> 5;
    int nbase = g*NPER + (blockIdx.x & 31)*64;
    int tn = threadIdx.x & 31;
    int to = threadIdx.x >> 5;

    for (int oc=0; oc<4; ++oc){
        ull acc2[4][8];
        #pragma unroll
        for (int np=0;np<4;np++)
            #pragma unroll
            for (int q=0;q<8;q++) acc2[np][q] = 0ull;

        for (int kc=0;kc<8;kc++){
            for (int t=threadIdx.x; t<64*32; t+=256){
                int n = t>>5, kk = t&31;
                int kglob = kc*32+kk;
                int node  = nbase + n;
                float v;
                if (kglob < 64)       v = g_x1[node*64  + kglob];
                else if (kglob < 128) v = g_x2[node*64  + (kglob-64)];
                else                  v = g_x3[node*128 + (kglob-128)];
                fbufT[kk*68+n] = v;
            }
            for (int t=threadIdx.x; t<32*256; t+=256){
                int kk = t>>8, o = t&255;
                wbuf[kk*260+o] = l1w[(kc*32+kk)*1024 + oc*256 + o];
            }
            __syncthreads();
            #pragma unroll 4
            for (int kk=0;kk<32;kk++){
                ulonglong2 fA = *(const ulonglong2*)(fbufT + kk*68 + to*8);
                ulonglong2 fB = *(const ulonglong2*)(fbufT + kk*68 + to*8 + 4);
                float4 wA = *(const float4*)(wbuf + kk*260 + tn*8);
                float4 wB = *(const float4*)(wbuf + kk*260 + tn*8 + 4);
                ull wd0 = dup2(wA.x), wd1 = dup2(wA.y);
                ull wd2 = dup2(wA.z), wd3 = dup2(wA.w);
                ull wd4 = dup2(wB.x), wd5 = dup2(wB.y);
                ull wd6 = dup2(wB.z), wd7 = dup2(wB.w);
                ull fp[4] = {fA.x, fA.y, fB.x, fB.y};
                #pragma unroll
                for (int np=0;np<4;np++){
                    FMA2(acc2[np][0], fp[np], wd0);
                    FMA2(acc2[np][1], fp[np], wd1);
                    FMA2(acc2[np][2], fp[np], wd2);
                    FMA2(acc2[np][3], fp[np], wd3);
                    FMA2(acc2[np][4], fp[np], wd4);
                    FMA2(acc2[np][5], fp[np], wd5);
                    FMA2(acc2[np][6], fp[np], wd6);
                    FMA2(acc2[np][7], fp[np], wd7);
                }
            }
            __syncthreads();
        }
        float m[8];
        #pragma unroll
        for (int q=0;q<8;q++){
            float best = -FLT_MAX;
            #pragma unroll
            for (int np=0;np<4;np++){
                float lo, hi; unpack2(acc2[np][q], lo, hi);
                best = fmaxf(best, fmaxf(lo, hi));
            }
            m[q] = best;
        }
        #pragma unroll
        for (int q=0;q<8;q++) wbuf[to*260 + tn*8 + q] = m[q];
        __syncthreads();
        {
            int o = threadIdx.x;
            float v = wbuf[o];
            #pragma unroll
            for (int t2=1;t2<8;t2++) v = fmaxf(v, wbuf[t2*260 + o]);
            v += l1b[oc*256 + o];
            atomicMaxFloat(&g_out2[g*1024 + oc*256 + o], v);
        }
        __syncthreads();
    }
}

// ---------------- head: MLP(1024->512->256->10) + log_softmax --------------
__global__ __launch_bounds__(256) void head_kernel(
    const float* __restrict__ m1w, const float* __restrict__ m1b,
    const float* __restrict__ m2w, const float* __restrict__ m2b,
    const float* __restrict__ m3w, const float* __restrict__ m3b,
    float* __restrict__ out)
{
    __shared__ float v[1024];
    __shared__ float h1[512];
    __shared__ float h2[256];
    __shared__ float z[10];
    int g = blockIdx.x;
    for (int t=threadIdx.x; t<1024; t+=256) v[t] = g_out2[g*1024+t];
    __syncthreads();
    #pragma unroll
    for (int oo=0;oo<2;oo++){
        int o = threadIdx.x + oo*256;
        float a = m1b[o];
        #pragma unroll 4
        for (int k=0;k<1024;k++) a += v[k]*m1w[k*512+o];
        h1[o] = fmaxf(a, 0.f);
    }
    __syncthreads();
    {
        int o = threadIdx.x;
        float a = m2b[o];
        #pragma unroll 4
        for (int k=0;k<512;k++) a += h1[k]*m2w[k*256+o];
        h2[o] = fmaxf(a, 0.f);
    }
    __syncthreads();
    if (threadIdx.x < 10){
        float a = m3b[threadIdx.x];
        for (int k=0;k<256;k++) a += h2[k]*m3w[k*10+threadIdx.x];
        z[threadIdx.x] = a;
    }
    __syncthreads();
    if (threadIdx.x == 0){
        float m = -FLT_MAX;
        for (int c=0;c<10;c++) m = fmaxf(m, z[c]);
        float s = 0.f;
        for (int c=0;c<10;c++) s += expf(z[c]-m);
        float l = logf(s);
        for (int c=0;c<10;c++) out[g*10+c] = z[c]-m-l;
    }
}

// ---------------- launch ----------------------------------------------------
extern "C" void kernel_launch(void* const* d_in, const int* in_sizes, int n_in,
                              void* d_out, int out_size)
{
    const float* pos  = (const float*)d_in[0];
    const float* xf   = (const float*)d_in[1];
    const float* c1w1 = (const float*)d_in[3];
    const float* c1b1 = (const float*)d_in[4];
    const float* c1w2 = (const float*)d_in[5];
    const float* c1b2 = (const float*)d_in[6];
    const float* c1w3 = (const float*)d_in[7];
    const float* c1b3 = (const float*)d_in[8];
    const float* c2w  = (const float*)d_in[9];
    const float* c2b  = (const float*)d_in[10];
    const float* c3w  = (const float*)d_in[11];
    const float* c3b  = (const float*)d_in[12];
    const float* l1w  = (const float*)d_in[13];
    const float* l1b  = (const float*)d_in[14];
    const float* m1w  = (const float*)d_in[15];
    const float* m1b  = (const float*)d_in[16];
    const float* m2w  = (const float*)d_in[17];
    const float* m2b  = (const float*)d_in[18];
    const float* m3w  = (const float*)d_in[19];
    const float* m3b  = (const float*)d_in[20];
    float* out = (float*)d_out;

    x0_kernel<<<NTOT/256, 256>>>(pos, xf);                         // 0
    sn_kernel<<<NTOT/256, 256>>>();                                // 1
    knn_kernel<<<NTOT/16, 512>>>();                                // 2
    conv1_kernel<<<NTOT/4, 128>>>(c1w1,c1b1,c1w2,c1b2,c1w3,c1b3);  // 3 (profiled)
    init_out2_kernel<<<(B_*1024+255)/256, 256>>>();                // 4
    uy_gemm2_kernel<<<dim3(NTOT/64, 1), 256>>>(c2w);
    gathermax2_kernel<<<NTOT/8, 256>>>(c2b);
    uy_gemm3_kernel<<<dim3(NTOT/64, 2), 256>>>(c3w);
    gathermax3_kernel<<<NTOT/8, 256>>>(c3b);
    lin1max_kernel<<<B_*32, 256>>>(l1w, l1b);
    head_kernel<<<B_, 256>>>(m1w,m1b,m2w,m2b,m3w,m3b,out);
}

// round 9
// speedup vs baseline: 1.3923x; 1.2153x over previous
#include <cuda_runtime.h>
#include <cfloat>
#include <math.h>

#define B_   16
#define NPER 2048
#define NTOT (B_*NPER)
#define KNN  20

typedef unsigned long long ull;

// ---------------- scratch (device globals; no runtime allocation) ----------
__device__ float4 g_x0[NTOT];
__device__ float  g_sn[NTOT];
__device__ int    g_idx[NTOT*KNN];
__device__ float  g_x1[NTOT*64];
__device__ float  g_x2[NTOT*64];
__device__ float  g_x3[NTOT*128];
__device__ float  g_u2[NTOT*64];
__device__ float  g_y2[NTOT*64];
__device__ float  g_u3[NTOT*128];
__device__ float  g_y3[NTOT*128];
__device__ float  g_out2[B_*1024];
__device__ float  g_h1[B_*512];

__device__ __forceinline__ void atomicMaxFloat(float* addr, float v){
    if (v >= 0.f) atomicMax((int*)addr, __float_as_int(v));
    else          atomicMin((unsigned int*)addr, (unsigned int)__float_as_int(v));
}

// packed f32x2 helpers (Blackwell)
#define FMA2(d,a,b) asm("fma.rn.f32x2 %0, %1, %2, %0;" : "+l"(d) : "l"(a), "l"(b))

__device__ __forceinline__ ull pack2(float lo, float hi){
    ull r;
    asm("mov.b64 %0, {%1, %2};" : "=l"(r) : "r"(__float_as_uint(lo)), "r"(__float_as_uint(hi)));
    return r;
}
__device__ __forceinline__ void unpack2(ull v, float& lo, float& hi){
    unsigned a, b;
    asm("mov.b64 {%0, %1}, %2;" : "=r"(a), "=r"(b) : "l"(v));
    lo = __uint_as_float(a); hi = __uint_as_float(b);
}

// ---------------- prep: x0 + sn + out2 init (fused) -------------------------
__global__ __launch_bounds__(256) void prep_kernel(const float* __restrict__ pos,
                                                   const float* __restrict__ xf){
    int i = blockIdx.x*256 + threadIdx.x;
    float4 p = make_float4(pos[i*3+0], pos[i*3+1], pos[i*3+2], xf[i]);
    g_x0[i] = p;
    g_sn[i] = p.x*p.x + p.y*p.y + p.z*p.z + p.w*p.w;
    if (i < B_*1024) g_out2[i] = -FLT_MAX;
}

// ---------------- kNN: warp per query (R6 proven) ---------------------------
__global__ __launch_bounds__(512) void knn_kernel()
{
    __shared__ float4 sp[NPER];
    __shared__ float  sn[NPER];
    const unsigned FULL = 0xFFFFFFFFu;
    int b    = blockIdx.x >> 7;
    int base = b * NPER;
    for (int j = threadIdx.x; j < NPER; j += 512){
        sp[j] = g_x0[base+j];
        sn[j] = g_sn[base+j];
    }
    __syncthreads();

    int lane = threadIdx.x & 31;
    int q    = (blockIdx.x & 127)*16 + (threadIdx.x >> 5);
    float4 p = sp[q];
    float  pn = sn[q];

    float bd = FLT_MAX;
    int   bi = 0;
    float worst = FLT_MAX;

    for (int s = 0; s < NPER; s += 32){
        int j = s + lane;
        float4 c = sp[j];
        float d = pn + sn[j] - 2.f*(p.x*c.x + p.y*c.y + p.z*c.z + p.w*c.w);
        if (j == q) d = FLT_MAX;
        unsigned m = __ballot_sync(FULL, d < worst);
        while (m){
            int src = __ffs(m) - 1; m &= m - 1;
            float dn = __shfl_sync(FULL, d, src);
            if (dn < worst){
                unsigned wm = __ballot_sync(FULL, (lane < KNN) && (bd == worst));
                int slot = __ffs(wm) - 1;
                if (lane == slot){ bd = dn; bi = s + src; }
                float v = (lane < KNN) ? bd : -FLT_MAX;
                #pragma unroll
                for (int t = 16; t > 0; t >>= 1)
                    v = fmaxf(v, __shfl_xor_sync(FULL, v, t));
                worst = v;
            }
        }
    }
    if (lane < KNN) g_idx[(base+q)*KNN + lane] = base + bi;
}

// ---------------- EdgeConv1: col-packed FMA2, 10-edge batches (R8 proven) ---
__global__ __launch_bounds__(128) void conv1_kernel(
    const float* __restrict__ w1, const float* __restrict__ b1,
    const float* __restrict__ w2, const float* __restrict__ b2,
    const float* __restrict__ w3, const float* __restrict__ b3)
{
    __shared__ __align__(16) float sW1 [4*64];
    __shared__ __align__(16) float sW1d[4*64];
    __shared__ __align__(16) float sW2t[64*68];
    __shared__ __align__(16) float sW3t[64*68];
    __shared__ float sb1[64];
    __shared__ __align__(16) float hb[4][10][64];

    for (int t = threadIdx.x; t < 64*64; t += 128){
        int c = t >> 6, o = t & 63;
        sW2t[o*68+c] = w2[t];
        sW3t[o*68+c] = w3[t];
    }
    for (int t = threadIdx.x; t < 4*64; t += 128){
        int c = t >> 6, o = t & 63;
        float top = w1[c*64+o], bot = w1[(c+4)*64+o];
        sW1[t] = bot; sW1d[t] = top - bot;
    }
    if (threadIdx.x < 64) sb1[threadIdx.x] = b1[threadIdx.x];
    __syncthreads();

    int wd = threadIdx.x >> 5, lane = threadIdx.x & 31;
    int i  = blockIdx.x * 4 + wd;
    int o0 = lane, o1 = lane + 32;
    float4 xi = g_x0[i];
    float base0 = sb1[o0] + xi.x*sW1d[o0] + xi.y*sW1d[64+o0] + xi.z*sW1d[128+o0] + xi.w*sW1d[192+o0];
    float base1 = sb1[o1] + xi.x*sW1d[o1] + xi.y*sW1d[64+o1] + xi.z*sW1d[128+o1] + xi.w*sW1d[192+o1];
    float b2v0 = b2[o0], b2v1 = b2[o1];
    float b3v0 = b3[o0], b3v1 = b3[o1];
    float mx0 = -FLT_MAX, mx1 = -FLT_MAX;
    const int* ip = g_idx + i*KNN;

    for (int half = 0; half < 2; half++){
        #pragma unroll
        for (int e=0;e<10;e++){
            int j = ip[half*10 + e];
            float4 xj = g_x0[j];
            float v0 = base0 + xj.x*sW1[o0] + xj.y*sW1[64+o0] + xj.z*sW1[128+o0] + xj.w*sW1[192+o0];
            float v1 = base1 + xj.x*sW1[o1] + xj.y*sW1[64+o1] + xj.z*sW1[128+o1] + xj.w*sW1[192+o1];
            hb[wd][e][o0] = fmaxf(v0, 0.f);
            hb[wd][e][o1] = fmaxf(v1, 0.f);
        }
        __syncwarp();
        ull a0[10], a1[10];
        #pragma unroll
        for (int e=0;e<10;e++){ a0[e]=0ull; a1[e]=0ull; }
        #pragma unroll
        for (int c8=0;c8<8;c8++){
            ulonglong2 w0a = *(const ulonglong2*)(sW2t + o0*68 + c8*8);
            ulonglong2 w0b = *(const ulonglong2*)(sW2t + o0*68 + c8*8 + 4);
            ulonglong2 w1a = *(const ulonglong2*)(sW2t + o1*68 + c8*8);
            ulonglong2 w1b = *(const ulonglong2*)(sW2t + o1*68 + c8*8 + 4);
            #pragma unroll
            for (int e=0;e<10;e++){
                ulonglong2 ha = *(const ulonglong2*)(&hb[wd][e][c8*8]);
                ulonglong2 hbv = *(const ulonglong2*)(&hb[wd][e][c8*8 + 4]);
                FMA2(a0[e], ha.x,  w0a.x);
                FMA2(a0[e], ha.y,  w0a.y);
                FMA2(a0[e], hbv.x, w0b.x);
                FMA2(a0[e], hbv.y, w0b.y);
                FMA2(a1[e], ha.x,  w1a.x);
                FMA2(a1[e], ha.y,  w1a.y);
                FMA2(a1[e], hbv.x, w1b.x);
                FMA2(a1[e], hbv.y, w1b.y);
            }
        }
        __syncwarp();
        #pragma unroll
        for (int e=0;e<10;e++){
            float lo, hi;
            unpack2(a0[e], lo, hi);
            hb[wd][e][o0] = fmaxf(lo + hi + b2v0, 0.f);
            unpack2(a1[e], lo, hi);
            hb[wd][e][o1] = fmaxf(lo + hi + b2v1, 0.f);
        }
        __syncwarp();
        #pragma unroll
        for (int e=0;e<10;e++){ a0[e]=0ull; a1[e]=0ull; }
        #pragma unroll
        for (int c8=0;c8<8;c8++){
            ulonglong2 w0a = *(const ulonglong2*)(sW3t + o0*68 + c8*8);
            ulonglong2 w0b = *(const ulonglong2*)(sW3t + o0*68 + c8*8 + 4);
            ulonglong2 w1a = *(const ulonglong2*)(sW3t + o1*68 + c8*8);
            ulonglong2 w1b = *(const ulonglong2*)(sW3t + o1*68 + c8*8 + 4);
            #pragma unroll
            for (int e=0;e<10;e++){
                ulonglong2 ha = *(const ulonglong2*)(&hb[wd][e][c8*8]);
                ulonglong2 hbv = *(const ulonglong2*)(&hb[wd][e][c8*8 + 4]);
                FMA2(a0[e], ha.x,  w0a.x);
                FMA2(a0[e], ha.y,  w0a.y);
                FMA2(a0[e], hbv.x, w0b.x);
                FMA2(a0[e], hbv.y, w0b.y);
                FMA2(a1[e], ha.x,  w1a.x);
                FMA2(a1[e], ha.y,  w1a.y);
                FMA2(a1[e], hbv.x, w1b.x);
                FMA2(a1[e], hbv.y, w1b.y);
            }
        }
        #pragma unroll
        for (int e=0;e<10;e++){
            float lo, hi;
            unpack2(a0[e], lo, hi);
            mx0 = fmaxf(mx0, lo + hi + b3v0);
            unpack2(a1[e], lo, hi);
            mx1 = fmaxf(mx1, lo + hi + b3v1);
        }
        __syncwarp();
    }
    g_x1[i*64+o0] = mx0;
    g_x1[i*64+o1] = mx1;
}

// ---------------- node-level GEMM: U = X@(Wt-Wb), Y = X@Wb ------------------
__device__ __forceinline__ void uy_gemm_body(
    const float* __restrict__ X, const float* __restrict__ W,
    float* __restrict__ U, float* __restrict__ Y, int OUT)
{
    __shared__ float fbuf[64*33];
    __shared__ float wbuf[32*132];
    int nbase = blockIdx.x * 64;
    int otile = blockIdx.y * 128;
    int tn = threadIdx.x & 15;
    int to = threadIdx.x >> 4;

    float acc[4][8];
    #pragma unroll
    for (int r=0;r<4;r++)
        #pragma unroll
        for (int q=0;q<8;q++) acc[r][q]=0.f;

    for (int kc=0;kc<2;kc++){
        for (int t=threadIdx.x; t<64*32; t+=256){
            int n=t>>5, kk=t&31;
            fbuf[n*33+kk] = X[(nbase+n)*64 + kc*32 + kk];
        }
        for (int t=threadIdx.x; t<32*128; t+=256){
            int kk=t>>7, oloc=t&127;
            int op = otile + oloc;
            int k  = kc*32+kk;
            wbuf[kk*132+oloc] = (op < OUT)
                ? (W[k*OUT + op] - W[(64+k)*OUT + op])
                : W[(64+k)*OUT + (op-OUT)];
        }
        __syncthreads();
        #pragma unroll 4
        for (int kk=0;kk<32;kk++){
            float f[4];
            #pragma unroll
            for (int r=0;r<4;r++) f[r] = fbuf[(to+16*r)*33+kk];
            float wv[8];
            #pragma unroll
            for (int q=0;q<8;q++) wv[q] = wbuf[kk*132 + tn + 16*q];
            #pragma unroll
            for (int r=0;r<4;r++)
                #pragma unroll
                for (int q=0;q<8;q++) acc[r][q] += f[r]*wv[q];
        }
        __syncthreads();
    }
    #pragma unroll
    for (int r=0;r<4;r++){
        int node = nbase + to + 16*r;
        #pragma unroll
        for (int q=0;q<8;q++){
            int op = otile + tn + 16*q;
            if (op < OUT) U[node*OUT + op]        = acc[r][q];
            else          Y[node*OUT + (op-OUT)]  = acc[r][q];
        }
    }
}

__global__ __launch_bounds__(256) void uy_gemm2_kernel(const float* __restrict__ W){
    uy_gemm_body(g_x1, W, g_u2, g_y2, 64);
}
__global__ __launch_bounds__(256) void uy_gemm3_kernel(const float* __restrict__ W){
    uy_gemm_body(g_x2, W, g_u3, g_y3, 128);
}

// ---------------- gather + elementwise max ----------------------------------
__global__ __launch_bounds__(256) void gathermax2_kernel(const float* __restrict__ b2){
    int wd = threadIdx.x >> 5, lane = threadIdx.x & 31;
    int i = blockIdx.x*8 + wd;
    const int* ip = g_idx + i*KNN;
    float2 mx = make_float2(-FLT_MAX, -FLT_MAX);
    #pragma unroll 5
    for (int t=0;t<KNN;t++){
        int j = ip[t];
        float2 v = *(const float2*)(g_y2 + j*64 + lane*2);
        mx.x = fmaxf(mx.x, v.x);
        mx.y = fmaxf(mx.y, v.y);
    }
    float2 u  = *(const float2*)(g_u2 + i*64 + lane*2);
    float2 bb = *(const float2*)(b2 + lane*2);
    float2 o;
    o.x = bb.x + u.x + mx.x;
    o.y = bb.y + u.y + mx.y;
    *(float2*)(g_x2 + i*64 + lane*2) = o;
}

__global__ __launch_bounds__(256) void gathermax3_kernel(const float* __restrict__ b3){
    int wd = threadIdx.x >> 5, lane = threadIdx.x & 31;
    int i = blockIdx.x*8 + wd;
    const int* ip = g_idx + i*KNN;
    float4 mx = make_float4(-FLT_MAX,-FLT_MAX,-FLT_MAX,-FLT_MAX);
    #pragma unroll 5
    for (int t=0;t<KNN;t++){
        int j = ip[t];
        float4 v = *(const float4*)(g_y3 + j*128 + lane*4);
        mx.x = fmaxf(mx.x, v.x);
        mx.y = fmaxf(mx.y, v.y);
        mx.z = fmaxf(mx.z, v.z);
        mx.w = fmaxf(mx.w, v.w);
    }
    float4 u  = *(const float4*)(g_u3 + i*128 + lane*4);
    float4 bb = *(const float4*)(b3 + lane*4);
    float4 o;
    o.x = bb.x + u.x + mx.x;
    o.y = bb.y + u.y + mx.y;
    o.z = bb.z + u.z + mx.z;
    o.w = bb.w + u.w + mx.w;
    *(float4*)(g_x3 + i*128 + lane*4) = o;
}

// ---------------- lin1 (256->1024) + pool: K-pair packed FMA2 ---------------
// 512 threads, 64 nodes/block, grid B_*32. Thread: tn=tid&31 -> outs tn+32q,
// to=tid>>5 (0..15) -> nodes to*4+r. Accs packed over K-pairs: acc[n][q],
// final = lo+hi. Weights staged as pre-packed k-pair ulls (lane-consecutive,
// conflict-free); features as packed k-pairs (warp-broadcast).
__global__ __launch_bounds__(512) void lin1max_kernel(
    const float* __restrict__ l1w, const float* __restrict__ l1b)
{
    __shared__ ull wp[16*256];    // [t][o]: (w[2t][o], w[2t+1][o])   32KB
    __shared__ ull fp[16*64];     // [t][n]: (f[n][2t], f[n][2t+1])    8KB
    int g     = blockIdx.x >> 5;
    int nbase = g*NPER + (blockIdx.x & 31)*64;
    int tn = threadIdx.x & 31;
    int to = threadIdx.x >> 5;   // 0..15

    for (int oc=0; oc<4; ++oc){
        ull acc[4][8];
        #pragma unroll
        for (int r=0;r<4;r++)
            #pragma unroll
            for (int q=0;q<8;q++) acc[r][q] = 0ull;

        for (int kc=0;kc<8;kc++){
            // stage features: 16 k-pairs x 64 nodes
            for (int s = threadIdx.x; s < 16*64; s += 512){
                int t = s >> 6, n = s & 63;
                int kglob = kc*32 + t*2;
                int node  = nbase + n;
                float2 v;
                if (kglob < 64)       v = *(const float2*)(g_x1 + node*64  + kglob);
                else if (kglob < 128) v = *(const float2*)(g_x2 + node*64  + (kglob-64));
                else                  v = *(const float2*)(g_x3 + node*128 + (kglob-128));
                fp[t*64+n] = pack2(v.x, v.y);
            }
            // stage weights: 16 k-pairs x 256 outs
            for (int s = threadIdx.x; s < 16*256; s += 512){
                int t = s >> 8, o = s & 255;
                int k = kc*32 + t*2;
                float w0 = l1w[k*1024     + oc*256 + o];
                float w1 = l1w[(k+1)*1024 + oc*256 + o];
                wp[t*256+o] = pack2(w0, w1);
            }
            __syncthreads();
            #pragma unroll
            for (int t=0;t<16;t++){
                ull f0 = fp[t*64 + to*4 + 0];
                ull f1 = fp[t*64 + to*4 + 1];
                ull f2 = fp[t*64 + to*4 + 2];
                ull f3 = fp[t*64 + to*4 + 3];
                ull w[8];
                #pragma unroll
                for (int q=0;q<8;q++) w[q] = wp[t*256 + tn + 32*q];
                #pragma unroll
                for (int q=0;q<8;q++){
                    FMA2(acc[0][q], f0, w[q]);
                    FMA2(acc[1][q], f1, w[q]);
                    FMA2(acc[2][q], f2, w[q]);
                    FMA2(acc[3][q], f3, w[q]);
                }
            }
            __syncthreads();
        }
        // epilogue: lo+hi, max over this thread's 4 nodes
        float m[8];
        #pragma unroll
        for (int q=0;q<8;q++){
            float best = -FLT_MAX;
            #pragma unroll
            for (int r=0;r<4;r++){
                float lo, hi; unpack2(acc[r][q], lo, hi);
                best = fmaxf(best, lo + hi);
            }
            m[q] = best;
        }
        // cross to-group reduction via smem (reuse wp as float buffer)
        float* red = (float*)wp;
        #pragma unroll
        for (int q=0;q<8;q++) red[to*256 + tn + 32*q] = m[q];
        __syncthreads();
        if (threadIdx.x < 256){
            int o = threadIdx.x;
            float v = red[o];
            #pragma unroll
            for (int r=1;r<16;r++) v = fmaxf(v, red[r*256 + o]);
            v += l1b[oc*256 + o];
            atomicMaxFloat(&g_out2[g*1024 + oc*256 + o], v);
        }
        __syncthreads();
    }
}

// ---------------- head1: 1024->512 + ReLU, k-split across thread halves -----
__global__ __launch_bounds__(256) void head1_kernel(
    const float* __restrict__ m1w, const float* __restrict__ m1b)
{
    __shared__ float v[1024];
    __shared__ float partial[256];
    int g     = blockIdx.x >> 2;
    int chunk = blockIdx.x & 3;       // 128 outs per block
    for (int t=threadIdx.x; t<1024; t+=256) v[t] = g_out2[g*1024+t];
    __syncthreads();
    int o    = chunk*128 + (threadIdx.x & 127);
    int half = threadIdx.x >> 7;
    float a = 0.f;
    #pragma unroll 8
    for (int k=half*512; k<half*512+512; k++) a += v[k]*m1w[k*512+o];
    partial[threadIdx.x] = a;
    __syncthreads();
    if (threadIdx.x < 128){
        float s = partial[threadIdx.x] + partial[threadIdx.x+128] + m1b[o];
        g_h1[g*512+o] = fmaxf(s, 0.f);
    }
}

// ---------------- head2: 512->256->10 + log_softmax -------------------------
__global__ __launch_bounds__(256) void head2_kernel(
    const float* __restrict__ m2w, const float* __restrict__ m2b,
    const float* __restrict__ m3w, const float* __restrict__ m3b,
    float* __restrict__ out)
{
    __shared__ float h1[512];
    __shared__ float h2[256];
    __shared__ float z[10];
    int g = blockIdx.x;
    for (int t=threadIdx.x; t<512; t+=256) h1[t] = g_h1[g*512+t];
    __syncthreads();
    {
        int o = threadIdx.x;
        float a = m2b[o];
        #pragma unroll 8
        for (int k=0;k<512;k++) a += h1[k]*m2w[k*256+o];
        h2[o] = fmaxf(a, 0.f);
    }
    __syncthreads();
    if (threadIdx.x < 10){
        float a = m3b[threadIdx.x];
        for (int k=0;k<256;k++) a += h2[k]*m3w[k*10+threadIdx.x];
        z[threadIdx.x] = a;
    }
    __syncthreads();
    if (threadIdx.x == 0){
        float m = -FLT_MAX;
        for (int c=0;c<10;c++) m = fmaxf(m, z[c]);
        float s = 0.f;
        for (int c=0;c<10;c++) s += expf(z[c]-m);
        float l = logf(s);
        for (int c=0;c<10;c++) out[g*10+c] = z[c]-m-l;
    }
}

// ---------------- launch ----------------------------------------------------
extern "C" void kernel_launch(void* const* d_in, const int* in_sizes, int n_in,
                              void* d_out, int out_size)
{
    const float* pos  = (const float*)d_in[0];
    const float* xf   = (const float*)d_in[1];
    const float* c1w1 = (const float*)d_in[3];
    const float* c1b1 = (const float*)d_in[4];
    const float* c1w2 = (const float*)d_in[5];
    const float* c1b2 = (const float*)d_in[6];
    const float* c1w3 = (const float*)d_in[7];
    const float* c1b3 = (const float*)d_in[8];
    const float* c2w  = (const float*)d_in[9];
    const float* c2b  = (const float*)d_in[10];
    const float* c3w  = (const float*)d_in[11];
    const float* c3b  = (const float*)d_in[12];
    const float* l1w  = (const float*)d_in[13];
    const float* l1b  = (const float*)d_in[14];
    const float* m1w  = (const float*)d_in[15];
    const float* m1b  = (const float*)d_in[16];
    const float* m2w  = (const float*)d_in[17];
    const float* m2b  = (const float*)d_in[18];
    const float* m3w  = (const float*)d_in[19];
    const float* m3b  = (const float*)d_in[20];
    float* out = (float*)d_out;

    prep_kernel<<<NTOT/256, 256>>>(pos, xf);                       // 0
    knn_kernel<<<NTOT/16, 512>>>();                                // 1
    conv1_kernel<<<NTOT/4, 128>>>(c1w1,c1b1,c1w2,c1b2,c1w3,c1b3);  // 2
    uy_gemm2_kernel<<<dim3(NTOT/64, 1), 256>>>(c2w);               // 3 (profiled)
    gathermax2_kernel<<<NTOT/8, 256>>>(c2b);                       // 4
    uy_gemm3_kernel<<<dim3(NTOT/64, 2), 256>>>(c3w);               // 5
    gathermax3_kernel<<<NTOT/8, 256>>>(c3b);                       // 6
    lin1max_kernel<<<B_*32, 512>>>(l1w, l1b);                      // 7
    head1_kernel<<<B_*4, 256>>>(m1w, m1b);                         // 8
    head2_kernel<<<B_, 256>>>(m2w, m2b, m3w, m3b, out);            // 9
}

// round 11
// speedup vs baseline: 1.8728x; 1.3451x over previous
#include <cuda_runtime.h>
#include <cuda_bf16.h>
#include <cfloat>
#include <math.h>

#define B_   16
#define NPER 2048
#define NTOT (B_*NPER)
#define KNN  20

typedef unsigned long long ull;

// ---------------- scratch (device globals; no runtime allocation) ----------
__device__ float4 g_x0[NTOT];
__device__ float  g_sn[NTOT];
__device__ int    g_idx[NTOT*KNN];
__device__ float  g_x1[NTOT*64];
__device__ float  g_x2[NTOT*64];
__device__ float  g_x3[NTOT*128];
__device__ float  g_u2[NTOT*64];
__device__ float  g_y2[NTOT*64];
__device__ float  g_u3[NTOT*128];
__device__ float  g_y3[NTOT*128];
__device__ float  g_out2[B_*1024];
__device__ float  g_h1[B_*512];
__device__ __align__(16) __nv_bfloat16 g_fhi[NTOT*256];
__device__ __align__(16) __nv_bfloat16 g_flo[NTOT*256];
__device__ __align__(16) __nv_bfloat16 g_whi[1024*256];
__device__ __align__(16) __nv_bfloat16 g_wlo[1024*256];

__device__ __forceinline__ void atomicMaxFloat(float* addr, float v){
    if (v >= 0.f) atomicMax((int*)addr, __float_as_int(v));
    else          atomicMin((unsigned int*)addr, (unsigned int)__float_as_int(v));
}

// packed f32x2 helpers (Blackwell)
#define FMA2(d,a,b) asm("fma.rn.f32x2 %0, %1, %2, %0;" : "+l"(d) : "l"(a), "l"(b))

__device__ __forceinline__ ull pack2(float lo, float hi){
    ull r;
    asm("mov.b64 %0, {%1, %2};" : "=l"(r) : "r"(__float_as_uint(lo)), "r"(__float_as_uint(hi)));
    return r;
}
__device__ __forceinline__ void unpack2(ull v, float& lo, float& hi){
    unsigned a, b;
    asm("mov.b64 {%0, %1}, %2;" : "=r"(a), "=r"(b) : "l"(v));
    lo = __uint_as_float(a); hi = __uint_as_float(b);
}
__device__ __forceinline__ unsigned packbf(__nv_bfloat16 a, __nv_bfloat16 b){
    __nv_bfloat162 t = __halves2bfloat162(a, b);
    return *reinterpret_cast<unsigned*>(&t);
}
// mma.sync m16n8k16 bf16 (HMMA path, base sm_80+ feature)
__device__ __forceinline__ void mma_bf16(float* d, const unsigned* a, const unsigned* b){
    asm volatile("mma.sync.aligned.m16n8k16.row.col.f32.bf16.bf16.f32 "
        "{%0,%1,%2,%3}, {%4,%5,%6,%7}, {%8,%9}, {%0,%1,%2,%3};"
        : "+f"(d[0]), "+f"(d[1]), "+f"(d[2]), "+f"(d[3])
        : "r"(a[0]), "r"(a[1]), "r"(a[2]), "r"(a[3]), "r"(b[0]), "r"(b[1]));
}

// ---------------- prep: x0 + sn + out2 init (fused) -------------------------
__global__ __launch_bounds__(256) void prep_kernel(const float* __restrict__ pos,
                                                   const float* __restrict__ xf){
    int i = blockIdx.x*256 + threadIdx.x;
    float4 p = make_float4(pos[i*3+0], pos[i*3+1], pos[i*3+2], xf[i]);
    g_x0[i] = p;
    g_sn[i] = p.x*p.x + p.y*p.y + p.z*p.z + p.w*p.w;
    if (i < B_*1024) g_out2[i] = -FLT_MAX;
}

// ---------------- weight conversion: l1w -> bf16 hi/lo, [o][k] transposed ---
__global__ __launch_bounds__(256) void wconv_kernel(const float* __restrict__ l1w){
    int i = blockIdx.x*256 + threadIdx.x;    // 1024*256
    int o = i & 1023, k = i >> 10;
    float w = l1w[k*1024 + o];
    __nv_bfloat16 h = __float2bfloat16(w);
    __nv_bfloat16 l = __float2bfloat16(w - __bfloat162float(h));
    g_whi[o*256 + k] = h;
    g_wlo[o*256 + k] = l;
}

// ---------------- feature conversion: x1|x2|x3 -> bf16 hi/lo [node][256] ----
__global__ __launch_bounds__(256) void fconv_kernel(){
    int i = blockIdx.x*256 + threadIdx.x;    // NTOT*128 pair-indices
    int node = i >> 7, kp = i & 127;
    int k = kp*2;
    float2 v;
    if (k < 64)       v = *(const float2*)(g_x1 + node*64  + k);
    else if (k < 128) v = *(const float2*)(g_x2 + node*64  + (k-64));
    else              v = *(const float2*)(g_x3 + node*128 + (k-128));
    __nv_bfloat16 h0 = __float2bfloat16(v.x);
    __nv_bfloat16 h1 = __float2bfloat16(v.y);
    __nv_bfloat16 l0 = __float2bfloat16(v.x - __bfloat162float(h0));
    __nv_bfloat16 l1 = __float2bfloat16(v.y - __bfloat162float(h1));
    *(unsigned*)(g_fhi + node*256 + k) = packbf(h0, h1);
    *(unsigned*)(g_flo + node*256 + k) = packbf(l0, l1);
}

// ---------------- kNN: warp per query (R6 proven) ---------------------------
__global__ __launch_bounds__(512) void knn_kernel()
{
    __shared__ float4 sp[NPER];
    __shared__ float  sn[NPER];
    const unsigned FULL = 0xFFFFFFFFu;
    int b    = blockIdx.x >> 7;
    int base = b * NPER;
    for (int j = threadIdx.x; j < NPER; j += 512){
        sp[j] = g_x0[base+j];
        sn[j] = g_sn[base+j];
    }
    __syncthreads();

    int lane = threadIdx.x & 31;
    int q    = (blockIdx.x & 127)*16 + (threadIdx.x >> 5);
    float4 p = sp[q];
    float  pn = sn[q];

    float bd = FLT_MAX;
    int   bi = 0;
    float worst = FLT_MAX;

    for (int s = 0; s < NPER; s += 32){
        int j = s + lane;
        float4 c = sp[j];
        float d = pn + sn[j] - 2.f*(p.x*c.x + p.y*c.y + p.z*c.z + p.w*c.w);
        if (j == q) d = FLT_MAX;
        unsigned m = __ballot_sync(FULL, d < worst);
        while (m){
            int src = __ffs(m) - 1; m &= m - 1;
            float dn = __shfl_sync(FULL, d, src);
            if (dn < worst){
                unsigned wm = __ballot_sync(FULL, (lane < KNN) && (bd == worst));
                int slot = __ffs(wm) - 1;
                if (lane == slot){ bd = dn; bi = s + src; }
                float v = (lane < KNN) ? bd : -FLT_MAX;
                #pragma unroll
                for (int t = 16; t > 0; t >>= 1)
                    v = fmaxf(v, __shfl_xor_sync(FULL, v, t));
                worst = v;
            }
        }
    }
    if (lane < KNN) g_idx[(base+q)*KNN + lane] = base + bi;
}

// ---------------- EdgeConv1: col-packed FMA2, 10-edge batches (R8 proven) ---
__global__ __launch_bounds__(128) void conv1_kernel(
    const float* __restrict__ w1, const float* __restrict__ b1,
    const float* __restrict__ w2, const float* __restrict__ b2,
    const float* __restrict__ w3, const float* __restrict__ b3)
{
    __shared__ __align__(16) float sW1 [4*64];
    __shared__ __align__(16) float sW1d[4*64];
    __shared__ __align__(16) float sW2t[64*68];
    __shared__ __align__(16) float sW3t[64*68];
    __shared__ float sb1[64];
    __shared__ __align__(16) float hb[4][10][64];

    for (int t = threadIdx.x; t < 64*64; t += 128){
        int c = t >> 6, o = t & 63;
        sW2t[o*68+c] = w2[t];
        sW3t[o*68+c] = w3[t];
    }
    for (int t = threadIdx.x; t < 4*64; t += 128){
        int c = t >> 6, o = t & 63;
        float top = w1[c*64+o], bot = w1[(c+4)*64+o];
        sW1[t] = bot; sW1d[t] = top - bot;
    }
    if (threadIdx.x < 64) sb1[threadIdx.x] = b1[threadIdx.x];
    __syncthreads();

    int wd = threadIdx.x >> 5, lane = threadIdx.x & 31;
    int i  = blockIdx.x * 4 + wd;
    int o0 = lane, o1 = lane + 32;
    float4 xi = g_x0[i];
    float base0 = sb1[o0] + xi.x*sW1d[o0] + xi.y*sW1d[64+o0] + xi.z*sW1d[128+o0] + xi.w*sW1d[192+o0];
    float base1 = sb1[o1] + xi.x*sW1d[o1] + xi.y*sW1d[64+o1] + xi.z*sW1d[128+o1] + xi.w*sW1d[192+o1];
    float b2v0 = b2[o0], b2v1 = b2[o1];
    float b3v0 = b3[o0], b3v1 = b3[o1];
    float mx0 = -FLT_MAX, mx1 = -FLT_MAX;
    const int* ip = g_idx + i*KNN;

    for (int half = 0; half < 2; half++){
        #pragma unroll
        for (int e=0;e<10;e++){
            int j = ip[half*10 + e];
            float4 xj = g_x0[j];
            float v0 = base0 + xj.x*sW1[o0] + xj.y*sW1[64+o0] + xj.z*sW1[128+o0] + xj.w*sW1[192+o0];
            float v1 = base1 + xj.x*sW1[o1] + xj.y*sW1[64+o1] + xj.z*sW1[128+o1] + xj.w*sW1[192+o1];
            hb[wd][e][o0] = fmaxf(v0, 0.f);
            hb[wd][e][o1] = fmaxf(v1, 0.f);
        }
        __syncwarp();
        ull a0[10], a1[10];
        #pragma unroll
        for (int e=0;e<10;e++){ a0[e]=0ull; a1[e]=0ull; }
        #pragma unroll
        for (int c8=0;c8<8;c8++){
            ulonglong2 w0a = *(const ulonglong2*)(sW2t + o0*68 + c8*8);
            ulonglong2 w0b = *(const ulonglong2*)(sW2t + o0*68 + c8*8 + 4);
            ulonglong2 w1a = *(const ulonglong2*)(sW2t + o1*68 + c8*8);
            ulonglong2 w1b = *(const ulonglong2*)(sW2t + o1*68 + c8*8 + 4);
            #pragma unroll
            for (int e=0;e<10;e++){
                ulonglong2 ha = *(const ulonglong2*)(&hb[wd][e][c8*8]);
                ulonglong2 hbv = *(const ulonglong2*)(&hb[wd][e][c8*8 + 4]);
                FMA2(a0[e], ha.x,  w0a.x);
                FMA2(a0[e], ha.y,  w0a.y);
                FMA2(a0[e], hbv.x, w0b.x);
                FMA2(a0[e], hbv.y, w0b.y);
                FMA2(a1[e], ha.x,  w1a.x);
                FMA2(a1[e], ha.y,  w1a.y);
                FMA2(a1[e], hbv.x, w1b.x);
                FMA2(a1[e], hbv.y, w1b.y);
            }
        }
        __syncwarp();
        #pragma unroll
        for (int e=0;e<10;e++){
            float lo, hi;
            unpack2(a0[e], lo, hi);
            hb[wd][e][o0] = fmaxf(lo + hi + b2v0, 0.f);
            unpack2(a1[e], lo, hi);
            hb[wd][e][o1] = fmaxf(lo + hi + b2v1, 0.f);
        }
        __syncwarp();
        #pragma unroll
        for (int e=0;e<10;e++){ a0[e]=0ull; a1[e]=0ull; }
        #pragma unroll
        for (int c8=0;c8<8;c8++){
            ulonglong2 w0a = *(const ulonglong2*)(sW3t + o0*68 + c8*8);
            ulonglong2 w0b = *(const ulonglong2*)(sW3t + o0*68 + c8*8 + 4);
            ulonglong2 w1a = *(const ulonglong2*)(sW3t + o1*68 + c8*8);
            ulonglong2 w1b = *(const ulonglong2*)(sW3t + o1*68 + c8*8 + 4);
            #pragma unroll
            for (int e=0;e<10;e++){
                ulonglong2 ha = *(const ulonglong2*)(&hb[wd][e][c8*8]);
                ulonglong2 hbv = *(const ulonglong2*)(&hb[wd][e][c8*8 + 4]);
                FMA2(a0[e], ha.x,  w0a.x);
                FMA2(a0[e], ha.y,  w0a.y);
                FMA2(a0[e], hbv.x, w0b.x);
                FMA2(a0[e], hbv.y, w0b.y);
                FMA2(a1[e], ha.x,  w1a.x);
                FMA2(a1[e], ha.y,  w1a.y);
                FMA2(a1[e], hbv.x, w1b.x);
                FMA2(a1[e], hbv.y, w1b.y);
            }
        }
        #pragma unroll
        for (int e=0;e<10;e++){
            float lo, hi;
            unpack2(a0[e], lo, hi);
            mx0 = fmaxf(mx0, lo + hi + b3v0);
            unpack2(a1[e], lo, hi);
            mx1 = fmaxf(mx1, lo + hi + b3v1);
        }
        __syncwarp();
    }
    g_x1[i*64+o0] = mx0;
    g_x1[i*64+o1] = mx1;
}

// ---------------- node-level GEMM: U = X@(Wt-Wb), Y = X@Wb ------------------
__device__ __forceinline__ void uy_gemm_body(
    const float* __restrict__ X, const float* __restrict__ W,
    float* __restrict__ U, float* __restrict__ Y, int OUT)
{
    __shared__ float fbuf[64*33];
    __shared__ float wbuf[32*132];
    int nbase = blockIdx.x * 64;
    int otile = blockIdx.y * 128;
    int tn = threadIdx.x & 15;
    int to = threadIdx.x >> 4;

    float acc[4][8];
    #pragma unroll
    for (int r=0;r<4;r++)
        #pragma unroll
        for (int q=0;q<8;q++) acc[r][q]=0.f;

    for (int kc=0;kc<2;kc++){
        for (int t=threadIdx.x; t<64*32; t+=256){
            int n=t>>5, kk=t&31;
            fbuf[n*33+kk] = X[(nbase+n)*64 + kc*32 + kk];
        }
        for (int t=threadIdx.x; t<32*128; t+=256){
            int kk=t>>7, oloc=t&127;
            int op = otile + oloc;
            int k  = kc*32+kk;
            wbuf[kk*132+oloc] = (op < OUT)
                ? (W[k*OUT + op] - W[(64+k)*OUT + op])
                : W[(64+k)*OUT + (op-OUT)];
        }
        __syncthreads();
        #pragma unroll 4
        for (int kk=0;kk<32;kk++){
            float f[4];
            #pragma unroll
            for (int r=0;r<4;r++) f[r] = fbuf[(to+16*r)*33+kk];
            float wv[8];
            #pragma unroll
            for (int q=0;q<8;q++) wv[q] = wbuf[kk*132 + tn + 16*q];
            #pragma unroll
            for (int r=0;r<4;r++)
                #pragma unroll
                for (int q=0;q<8;q++) acc[r][q] += f[r]*wv[q];
        }
        __syncthreads();
    }
    #pragma unroll
    for (int r=0;r<4;r++){
        int node = nbase + to + 16*r;
        #pragma unroll
        for (int q=0;q<8;q++){
            int op = otile + tn + 16*q;
            if (op < OUT) U[node*OUT + op]        = acc[r][q];
            else          Y[node*OUT + (op-OUT)]  = acc[r][q];
        }
    }
}

__global__ __launch_bounds__(256) void uy_gemm2_kernel(const float* __restrict__ W){
    uy_gemm_body(g_x1, W, g_u2, g_y2, 64);
}
__global__ __launch_bounds__(256) void uy_gemm3_kernel(const float* __restrict__ W){
    uy_gemm_body(g_x2, W, g_u3, g_y3, 128);
}

// ---------------- gather + elementwise max ----------------------------------
__global__ __launch_bounds__(256) void gathermax2_kernel(const float* __restrict__ b2){
    int wd = threadIdx.x >> 5, lane = threadIdx.x & 31;
    int i = blockIdx.x*8 + wd;
    const int* ip = g_idx + i*KNN;
    float2 mx = make_float2(-FLT_MAX, -FLT_MAX);
    #pragma unroll 5
    for (int t=0;t<KNN;t++){
        int j = ip[t];
        float2 v = *(const float2*)(g_y2 + j*64 + lane*2);
        mx.x = fmaxf(mx.x, v.x);
        mx.y = fmaxf(mx.y, v.y);
    }
    float2 u  = *(const float2*)(g_u2 + i*64 + lane*2);
    float2 bb = *(const float2*)(b2 + lane*2);
    float2 o;
    o.x = bb.x + u.x + mx.x;
    o.y = bb.y + u.y + mx.y;
    *(float2*)(g_x2 + i*64 + lane*2) = o;
}

__global__ __launch_bounds__(256) void gathermax3_kernel(const float* __restrict__ b3){
    int wd = threadIdx.x >> 5, lane = threadIdx.x & 31;
    int i = blockIdx.x*8 + wd;
    const int* ip = g_idx + i*KNN;
    float4 mx = make_float4(-FLT_MAX,-FLT_MAX,-FLT_MAX,-FLT_MAX);
    #pragma unroll 5
    for (int t=0;t<KNN;t++){
        int j = ip[t];
        float4 v = *(const float4*)(g_y3 + j*128 + lane*4);
        mx.x = fmaxf(mx.x, v.x);
        mx.y = fmaxf(mx.y, v.y);
        mx.z = fmaxf(mx.z, v.z);
        mx.w = fmaxf(mx.w, v.w);
    }
    float4 u  = *(const float4*)(g_u3 + i*128 + lane*4);
    float4 bb = *(const float4*)(b3 + lane*4);
    float4 o;
    o.x = bb.x + u.x + mx.x;
    o.y = bb.y + u.y + mx.y;
    o.z = bb.z + u.z + mx.z;
    o.w = bb.w + u.w + mx.w;
    *(float4*)(g_x3 + i*128 + lane*4) = o;
}

// ---------------- lin1 (256->1024) + pool via mma.sync bf16 split-2 ---------
// Block: 256 thr (8 warps), tile 128 nodes x 128 outs, K=256 in 8 chunks of 32.
// Warp w: wn=w&1 (node half, 64 nodes), wo=w>>1 (out quarter, 32 outs).
// Terms: Ahi*Bhi + Ahi*Blo + Alo*Bhi (lo*lo dropped, ~4e-6 relative).
__global__ __launch_bounds__(256) void lin1mma_kernel(const float* __restrict__ l1b)
{
    __shared__ __align__(16) __nv_bfloat16 sAhi[128*40];
    __shared__ __align__(16) __nv_bfloat16 sAlo[128*40];
    __shared__ __align__(16) __nv_bfloat16 sBhi[128*40];
    __shared__ __align__(16) __nv_bfloat16 sBlo[128*40];

    int tid  = threadIdx.x;
    int wid  = tid >> 5, lane = tid & 31;
    int wn   = wid & 1, wo = wid >> 1;
    int nbase = blockIdx.x * 128;
    int obase = blockIdx.y * 128;
    int g     = blockIdx.x >> 4;

    float d[4][4][4];   // [mt][nt][reg]
    #pragma unroll
    for (int mt=0;mt<4;mt++)
        #pragma unroll
        for (int nt=0;nt<4;nt++)
            #pragma unroll
            for (int r=0;r<4;r++) d[mt][nt][r] = 0.f;

    int srow = tid >> 1, shalf = tid & 1;

    for (int kc = 0; kc < 8; kc++){
        // ---- stage A/B chunk (32 k) as 2x uint4 per array per thread ----
        {
            size_t fo = (size_t)(nbase + srow)*256 + kc*32 + shalf*16;
            const uint4* pah = (const uint4*)(g_fhi + fo);
            const uint4* pal = (const uint4*)(g_flo + fo);
            uint4 a0 = pah[0], a1 = pah[1];
            uint4 l0 = pal[0], l1 = pal[1];
            size_t wo2 = (size_t)(obase + srow)*256 + kc*32 + shalf*16;
            const uint4* pbh = (const uint4*)(g_whi + wo2);
            const uint4* pbl = (const uint4*)(g_wlo + wo2);
            uint4 b0 = pbh[0], b1 = pbh[1];
            uint4 m0 = pbl[0], m1 = pbl[1];
            int so = srow*40 + shalf*16;
            *(uint4*)(sAhi + so) = a0; *(uint4*)(sAhi + so + 8) = a1;
            *(uint4*)(sAlo + so) = l0; *(uint4*)(sAlo + so + 8) = l1;
            *(uint4*)(sBhi + so) = b0; *(uint4*)(sBhi + so + 8) = b1;
            *(uint4*)(sBlo + so) = m0; *(uint4*)(sBlo + so + 8) = m1;
        }
        __syncthreads();
        // ---- 2 k-steps of 16 ----
        #pragma unroll
        for (int ks = 0; ks < 2; ks++){
            int kof = ks*16 + (lane & 3)*2;
            unsigned bh[4][2], bl[4][2];
            #pragma unroll
            for (int nt=0; nt<4; nt++){
                int n = wo*32 + nt*8 + (lane >> 2);
                bh[nt][0] = *(const unsigned*)(sBhi + n*40 + kof);
                bh[nt][1] = *(const unsigned*)(sBhi + n*40 + kof + 8);
                bl[nt][0] = *(const unsigned*)(sBlo + n*40 + kof);
                bl[nt][1] = *(const unsigned*)(sBlo + n*40 + kof + 8);
            }
            unsigned a[4][4];
            #pragma unroll
            for (int mt=0; mt<4; mt++){
                int r = wn*64 + mt*16 + (lane >> 2);
                a[mt][0] = *(const unsigned*)(sAhi + r*40     + kof);
                a[mt][1] = *(const unsigned*)(sAhi + (r+8)*40 + kof);
                a[mt][2] = *(const unsigned*)(sAhi + r*40     + kof + 8);
                a[mt][3] = *(const unsigned*)(sAhi + (r+8)*40 + kof + 8);
            }
            #pragma unroll
            for (int mt=0; mt<4; mt++)
                #pragma unroll
                for (int nt=0; nt<4; nt++){
                    mma_bf16(d[mt][nt], a[mt], bh[nt]);   // Ahi*Bhi
                    mma_bf16(d[mt][nt], a[mt], bl[nt]);   // Ahi*Blo
                }
            #pragma unroll
            for (int mt=0; mt<4; mt++){
                int r = wn*64 + mt*16 + (lane >> 2);
                a[mt][0] = *(const unsigned*)(sAlo + r*40     + kof);
                a[mt][1] = *(const unsigned*)(sAlo + (r+8)*40 + kof);
                a[mt][2] = *(const unsigned*)(sAlo + r*40     + kof + 8);
                a[mt][3] = *(const unsigned*)(sAlo + (r+8)*40 + kof + 8);
            }
            #pragma unroll
            for (int mt=0; mt<4; mt++)
                #pragma unroll
                for (int nt=0; nt<4; nt++)
                    mma_bf16(d[mt][nt], a[mt], bh[nt]);   // Alo*Bhi
        }
        __syncthreads();
    }

    // ---- epilogue: max over nodes, then atomicMax into g_out2 ----
    #pragma unroll
    for (int nt=0; nt<4; nt++){
        float m0 = -FLT_MAX, m1 = -FLT_MAX;
        #pragma unroll
        for (int mt=0; mt<4; mt++){
            m0 = fmaxf(m0, fmaxf(d[mt][nt][0], d[mt][nt][2]));
            m1 = fmaxf(m1, fmaxf(d[mt][nt][1], d[mt][nt][3]));
        }
        #pragma unroll
        for (int off=4; off<32; off<<=1){
            m0 = fmaxf(m0, __shfl_xor_sync(0xFFFFFFFFu, m0, off));
            m1 = fmaxf(m1, __shfl_xor_sync(0xFFFFFFFFu, m1, off));
        }
        if (lane < 4){
            int col = obase + wo*32 + nt*8 + lane*2;
            atomicMaxFloat(&g_out2[g*1024 + col    ], m0 + l1b[col]);
            atomicMaxFloat(&g_out2[g*1024 + col + 1], m1 + l1b[col+1]);
        }
    }
}

// ---------------- head1: 1024->512 + ReLU ------------------------------------
__global__ __launch_bounds__(256) void head1_kernel(
    const float* __restrict__ m1w, const float* __restrict__ m1b)
{
    __shared__ float v[1024];
    __shared__ float partial[256];
    int g     = blockIdx.x >> 2;
    int chunk = blockIdx.x & 3;
    for (int t=threadIdx.x; t<1024; t+=256) v[t] = g_out2[g*1024+t];
    __syncthreads();
    int o    = chunk*128 + (threadIdx.x & 127);
    int half = threadIdx.x >> 7;
    float a = 0.f;
    #pragma unroll 8
    for (int k=half*512; k<half*512+512; k++) a += v[k]*m1w[k*512+o];
    partial[threadIdx.x] = a;
    __syncthreads();
    if (threadIdx.x < 128){
        float s = partial[threadIdx.x] + partial[threadIdx.x+128] + m1b[o];
        g_h1[g*512+o] = fmaxf(s, 0.f);
    }
}

// ---------------- head2: 512->256->10 + log_softmax -------------------------
__global__ __launch_bounds__(256) void head2_kernel(
    const float* __restrict__ m2w, const float* __restrict__ m2b,
    const float* __restrict__ m3w, const float* __restrict__ m3b,
    float* __restrict__ out)
{
    __shared__ float h1[512];
    __shared__ float h2[256];
    __shared__ float z[10];
    int g = blockIdx.x;
    for (int t=threadIdx.x; t<512; t+=256) h1[t] = g_h1[g*512+t];
    __syncthreads();
    {
        int o = threadIdx.x;
        float a = m2b[o];
        #pragma unroll 8
        for (int k=0;k<512;k++) a += h1[k]*m2w[k*256+o];
        h2[o] = fmaxf(a, 0.f);
    }
    __syncthreads();
    if (threadIdx.x < 10){
        float a = m3b[threadIdx.x];
        for (int k=0;k<256;k++) a += h2[k]*m3w[k*10+threadIdx.x];
        z[threadIdx.x] = a;
    }
    __syncthreads();
    if (threadIdx.x == 0){
        float m = -FLT_MAX;
        for (int c=0;c<10;c++) m = fmaxf(m, z[c]);
        float s = 0.f;
        for (int c=0;c<10;c++) s += expf(z[c]-m);
        float l = logf(s);
        for (int c=0;c<10;c++) out[g*10+c] = z[c]-m-l;
    }
}

// ---------------- launch ----------------------------------------------------
extern "C" void kernel_launch(void* const* d_in, const int* in_sizes, int n_in,
                              void* d_out, int out_size)
{
    const float* pos  = (const float*)d_in[0];
    const float* xf   = (const float*)d_in[1];
    const float* c1w1 = (const float*)d_in[3];
    const float* c1b1 = (const float*)d_in[4];
    const float* c1w2 = (const float*)d_in[5];
    const float* c1b2 = (const float*)d_in[6];
    const float* c1w3 = (const float*)d_in[7];
    const float* c1b3 = (const float*)d_in[8];
    const float* c2w  = (const float*)d_in[9];
    const float* c2b  = (const float*)d_in[10];
    const float* c3w  = (const float*)d_in[11];
    const float* c3b  = (const float*)d_in[12];
    const float* l1w  = (const float*)d_in[13];
    const float* l1b  = (const float*)d_in[14];
    const float* m1w  = (const float*)d_in[15];
    const float* m1b  = (const float*)d_in[16];
    const float* m2w  = (const float*)d_in[17];
    const float* m2b  = (const float*)d_in[18];
    const float* m3w  = (const float*)d_in[19];
    const float* m3b  = (const float*)d_in[20];
    float* out = (float*)d_out;

    prep_kernel<<<NTOT/256, 256>>>(pos, xf);                       // 0
    knn_kernel<<<NTOT/16, 512>>>();                                // 1
    conv1_kernel<<<NTOT/4, 128>>>(c1w1,c1b1,c1w2,c1b2,c1w3,c1b3);  // 2
    uy_gemm2_kernel<<<dim3(NTOT/64, 1), 256>>>(c2w);               // 3 (profiled)
    gathermax2_kernel<<<NTOT/8, 256>>>(c2b);                       // 4
    uy_gemm3_kernel<<<dim3(NTOT/64, 2), 256>>>(c3w);               // 5
    gathermax3_kernel<<<NTOT/8, 256>>>(c3b);                       // 6
    wconv_kernel<<<1024*256/256, 256>>>(l1w);                      // 7
    fconv_kernel<<<NTOT*128/256, 256>>>();                         // 8
    lin1mma_kernel<<<dim3(NTOT/128, 8), 256>>>(l1b);               // 9
    head1_kernel<<<B_*4, 256>>>(m1w, m1b);                         // 10
    head2_kernel<<<B_, 256>>>(m2w, m2b, m3w, m3b, out);            // 11
}